// round 5
// baseline (speedup 1.0000x reference)
#include <cuda_runtime.h>
#include <cuda_fp16.h>
#include <cstdint>

#define NTOK 4096
#define HH   1024
#define VV   32000
#define VSP  125          // 125 * 256 = 32000 vocab splits
#define TTL  32           // 32 * 128 = 4096 token tiles
#define NKC  16           // 16 * 64 = 1024 k-chunks
#define AROWB 144         // 72 fp16 per smem row (64 data + 8 pad)
#define ATILEB (128*AROWB)  // 18432
#define BTILEB (256*AROWB)  // 36864
#define STGB  (ATILEB + BTILEB)  // 55296
#define DSMEM (2*STGB)           // 110592

// ---------------- device scratch (no allocations allowed) -------------------
__device__ __align__(256) __half g_xb[(size_t)2*NTOK*HH];   // 16.8 MB
__device__ __align__(256) __half g_wb[(size_t)2*VV*HH];     // 131 MB
__device__ float g_pm[(size_t)2*NTOK*VSP];
__device__ float g_ps[(size_t)2*NTOK*VSP];
__device__ float g_sel[2*NTOK];
__device__ float g_bsum[32];
__device__ float g_bmsk[32];

__device__ __forceinline__ uint32_t smem_u32(const void* p){
    uint32_t a;
    asm("{ .reg .u64 t; cvta.to.shared.u64 t, %1; cvt.u32.u64 %0, t; }" : "=r"(a) : "l"(p));
    return a;
}

// ================= fp32 -> fp16 conversion (linear layout) ==================
__global__ void k_convert(const float* __restrict__ s0, const float* __restrict__ s1,
                          __half* __restrict__ dst, size_t per_model_vec4){
    size_t g = (size_t)blockIdx.x*blockDim.x + threadIdx.x;
    if (g >= 2*per_model_vec4) return;
    int m = (int)(g / per_model_vec4);
    size_t i = g - (size_t)m*per_model_vec4;
    const float* src = m ? s1 : s0;
    float4 v = reinterpret_cast<const float4*>(src)[i];
    __half2 lo = __floats2half2_rn(v.x, v.y);
    __half2 hi = __floats2half2_rn(v.z, v.w);
    uint2 o;
    o.x = *reinterpret_cast<uint32_t*>(&lo);
    o.y = *reinterpret_cast<uint32_t*>(&hi);
    reinterpret_cast<uint2*>(dst + (size_t)m*per_model_vec4*4)[i] = o;
}

// ================= main GEMM (mma.sync fp16) + fused online-LSE =============
// grid: (VSP=125, TTL=32, 2), block 256. CTA tile 128(M) x 256(N).
// 8 warps as 2(M) x 4(N): warp tile 64 x 64.
__global__ void __launch_bounds__(256,1) k_gemm(){
    extern __shared__ __align__(16) unsigned char dsm[];
    const int tid = threadIdx.x, wid = tid>>5, lane = tid&31;
    const int vs = blockIdx.x, tt = blockIdx.y, model = blockIdx.z;
    const int wm = wid>>2, wn = wid&3;
    uint32_t sbase = smem_u32(dsm);
    const unsigned char* asrc = (const unsigned char*)(g_xb + ((size_t)model*NTOK + (size_t)tt*128)*HH);
    const unsigned char* bsrc = (const unsigned char*)(g_wb + ((size_t)model*VV   + (size_t)vs*256)*HH);

    float acc[4][8][4];
    #pragma unroll
    for (int a=0;a<4;a++)
        #pragma unroll
        for (int b=0;b<8;b++)
            #pragma unroll
            for (int c=0;c<4;c++) acc[a][b][c]=0.f;

    // ---- async chunk loader: A 128 rows + B 256 rows, 128B each ------------
    // (128+256)*8 = 3072 chunks of 16B; 256 threads x 12 iters
    #define LOAD_CHUNK(kc) do{ \
        int _s = (kc)&1; \
        uint32_t Ab = sbase + _s*STGB, Bb = Ab + ATILEB; \
        _Pragma("unroll") \
        for (int it = 0; it < 12; it++){ \
            int idx = tid + it*256; \
            int row = idx>>3, grp = idx&7; \
            if (it < 4){ \
                uint32_t da = Ab + row*AROWB + grp*16; \
                const unsigned char* sa = asrc + (size_t)row*2048 + (size_t)(kc)*128 + grp*16; \
                asm volatile("cp.async.cg.shared.global [%0], [%1], 16;" :: "r"(da), "l"(sa)); \
            } else { \
                int br = row - 128; \
                uint32_t db = Bb + br*AROWB + grp*16; \
                const unsigned char* sb = bsrc + (size_t)br*2048 + (size_t)(kc)*128 + grp*16; \
                asm volatile("cp.async.cg.shared.global [%0], [%1], 16;" :: "r"(db), "l"(sb)); \
            } \
        } \
        asm volatile("cp.async.commit_group;"); \
    }while(0)

    LOAD_CHUNK(0);
    #pragma unroll 1
    for (int kc = 0; kc < NKC; kc++){
        int s = kc & 1;
        asm volatile("cp.async.wait_group 0;");   // chunk kc resident (own ops)
        __syncthreads();                          // publish + protect stage s^1
        if (kc + 1 < NKC) LOAD_CHUNK(kc+1);       // overlaps with compute below
        uint32_t Ab = sbase + s*STGB, Bb = Ab + ATILEB;
        #pragma unroll
        for (int ks = 0; ks < 4; ks++){
            uint32_t af[4][4], bf[4][4];
            #pragma unroll
            for (int mt = 0; mt < 4; mt++){
                int row = wm*64 + mt*16 + (lane&15);
                int col = ks*16 + (lane>>4)*8;
                uint32_t a = Ab + row*AROWB + col*2;
                asm volatile("ldmatrix.sync.aligned.m8n8.x4.shared.b16 {%0,%1,%2,%3}, [%4];"
                    : "=r"(af[mt][0]),"=r"(af[mt][1]),"=r"(af[mt][2]),"=r"(af[mt][3]) : "r"(a));
            }
            #pragma unroll
            for (int p = 0; p < 4; p++){
                int row = wn*64 + p*16 + (lane&7) + ((lane>>4)<<3);
                int col = ks*16 + ((lane>>3)&1)*8;
                uint32_t a = Bb + row*AROWB + col*2;
                asm volatile("ldmatrix.sync.aligned.m8n8.x4.shared.b16 {%0,%1,%2,%3}, [%4];"
                    : "=r"(bf[p][0]),"=r"(bf[p][1]),"=r"(bf[p][2]),"=r"(bf[p][3]) : "r"(a));
            }
            #pragma unroll
            for (int mt = 0; mt < 4; mt++)
                #pragma unroll
                for (int nt = 0; nt < 8; nt++){
                    uint32_t b0 = bf[nt>>1][(nt&1)*2], b1 = bf[nt>>1][(nt&1)*2+1];
                    asm volatile("mma.sync.aligned.m16n8k16.row.col.f32.f16.f16.f32 "
                        "{%0,%1,%2,%3}, {%4,%5,%6,%7}, {%8,%9}, {%0,%1,%2,%3};"
                        : "+f"(acc[mt][nt][0]),"+f"(acc[mt][nt][1]),"+f"(acc[mt][nt][2]),"+f"(acc[mt][nt][3])
                        : "r"(af[mt][0]),"r"(af[mt][1]),"r"(af[mt][2]),"r"(af[mt][3]),
                          "r"(b0),"r"(b1));
                }
        }
    }
    __syncthreads();

    // ---- fused epilogue: per-token-row (max, sumexp) over this 256-col slab -
    float* smM = (float*)dsm;           // [8][64]
    float* smS = smM + 8*64;
    int q = lane>>2;
    #pragma unroll
    for (int mt = 0; mt < 4; mt++){
        float m0=-3e38f, m1=-3e38f;
        #pragma unroll
        for (int nt = 0; nt < 8; nt++){
            m0 = fmaxf(m0, fmaxf(acc[mt][nt][0], acc[mt][nt][1]));
            m1 = fmaxf(m1, fmaxf(acc[mt][nt][2], acc[mt][nt][3]));
        }
        #pragma unroll
        for (int o = 1; o <= 2; o <<= 1){
            m0 = fmaxf(m0, __shfl_xor_sync(0xFFFFFFFFu, m0, o));
            m1 = fmaxf(m1, __shfl_xor_sync(0xFFFFFFFFu, m1, o));
        }
        float s0 = 0.f, s1 = 0.f;
        #pragma unroll
        for (int nt = 0; nt < 8; nt++){
            s0 += __expf(acc[mt][nt][0]-m0) + __expf(acc[mt][nt][1]-m0);
            s1 += __expf(acc[mt][nt][2]-m1) + __expf(acc[mt][nt][3]-m1);
        }
        #pragma unroll
        for (int o = 1; o <= 2; o <<= 1){
            s0 += __shfl_xor_sync(0xFFFFFFFFu, s0, o);
            s1 += __shfl_xor_sync(0xFFFFFFFFu, s1, o);
        }
        if ((lane&3) == 0){
            int r = mt*16 + q;
            smM[wid*64 + r]     = m0;  smS[wid*64 + r]     = s0;
            smM[wid*64 + r + 8] = m1;  smS[wid*64 + r + 8] = s1;
        }
    }
    __syncthreads();
    if (tid < 128){
        int wm2 = tid>>6, r = tid&63;
        float M = -3e38f;
        #pragma unroll
        for (int w = 0; w < 4; w++) M = fmaxf(M, smM[(wm2*4+w)*64 + r]);
        float S = 0.f;
        #pragma unroll
        for (int w = 0; w < 4; w++) S += smS[(wm2*4+w)*64 + r] * __expf(smM[(wm2*4+w)*64 + r] - M);
        int tok = tt*128 + tid;
        size_t o = ((size_t)(model*NTOK + tok))*VSP + vs;
        g_pm[o] = M; g_ps[o] = S;
    }
}

// ================= exact fp32 selected logits ================================
__global__ void k_sel(const float* __restrict__ x, const float* __restrict__ w,
                      const float* __restrict__ rx, const float* __restrict__ rw,
                      const int* __restrict__ ids){
    int gw = (int)((blockIdx.x*blockDim.x + threadIdx.x) >> 5);
    int lane = threadIdx.x & 31;
    if (gw >= 2*NTOK) return;
    int m = gw >> 12, t = gw & (NTOK-1);
    const float* X = m ? rx : x;
    const float* W = m ? rw : w;
    int id = ids[t];
    const float4* xa = (const float4*)(X + (size_t)t*HH);
    const float4* wa = (const float4*)(W + (size_t)id*HH);
    float acc = 0.f;
    #pragma unroll 8
    for (int i = lane; i < 256; i += 32){
        float4 a = xa[i], b = wa[i];
        acc += a.x*b.x + a.y*b.y + a.z*b.z + a.w*b.w;
    }
    #pragma unroll
    for (int o = 16; o; o >>= 1) acc += __shfl_xor_sync(0xFFFFFFFFu, acc, o);
    if (!lane) g_sel[gw] = acc;
}

// ================= per-token loss + deterministic block sums =================
__global__ void k_reduce(const float* __restrict__ adv, const int* __restrict__ mask){
    int t = blockIdx.x*128 + threadIdx.x;   // 32 x 128 = 4096
    float lse[2];
    #pragma unroll
    for (int m = 0; m < 2; m++){
        const float* pm = g_pm + ((size_t)(m*NTOK + t))*VSP;
        const float* ps = g_ps + ((size_t)(m*NTOK + t))*VSP;
        float mx = -3e38f;
        for (int v = 0; v < VSP; v++) mx = fmaxf(mx, pm[v]);
        float sv = 0.f;
        for (int v = 0; v < VSP; v++) sv += ps[v] * __expf(pm[v] - mx);
        lse[m] = mx + logf(sv);
    }
    float lp  = g_sel[t]        - lse[0];
    float rlp = g_sel[NTOK + t] - lse[1];
    float d = rlp - lp;
    float kl = expf(d) - d - 1.f;
    float mk = (float)mask[t];
    float pl = (-adv[t >> 10] + 0.1f*kl) * mk;

    __shared__ float sh[128], shm[128];
    sh[threadIdx.x] = pl; shm[threadIdx.x] = mk;
    __syncthreads();
    for (int o = 64; o; o >>= 1){
        if (threadIdx.x < o){ sh[threadIdx.x] += sh[threadIdx.x+o]; shm[threadIdx.x] += shm[threadIdx.x+o]; }
        __syncthreads();
    }
    if (!threadIdx.x){ g_bsum[blockIdx.x] = sh[0]; g_bmsk[blockIdx.x] = shm[0]; }
}

__global__ void k_final(float* out){
    float s = 0.f, m = 0.f;
    for (int i = 0; i < 32; i++){ s += g_bsum[i]; m += g_bmsk[i]; }
    out[0] = s / fmaxf(m, 1.f);
}

// ================= launch =====================================================
extern "C" void kernel_launch(void* const* d_in, const int* in_sizes, int n_in,
                              void* d_out, int out_size){
    const float* x   = (const float*)d_in[0];
    const float* w   = (const float*)d_in[1];
    const float* rx  = (const float*)d_in[2];
    const float* rw  = (const float*)d_in[3];
    const float* adv = (const float*)d_in[4];
    const int* ids   = (const int*)d_in[5];
    const int* mask  = (const int*)d_in[6];
    float* out = (float*)d_out;

    cudaFuncSetAttribute(k_gemm, cudaFuncAttributeMaxDynamicSharedMemorySize, DSMEM);

    {   size_t v4 = (size_t)NTOK*HH/4;   // hidden convert
        k_convert<<<(unsigned)((2*v4 + 255)/256), 256>>>(x, rx, g_xb, v4);
    }
    {   size_t v4 = (size_t)VV*HH/4;     // weight convert
        k_convert<<<(unsigned)((2*v4 + 255)/256), 256>>>(w, rw, g_wb, v4);
    }
    k_gemm<<<dim3(VSP, TTL, 2), 256, DSMEM>>>();
    k_sel<<<(2*NTOK*32 + 255)/256, 256>>>(x, w, rx, rw, ids);
    k_reduce<<<32, 128>>>(adv, mask);
    k_final<<<1, 1>>>(out);
}

// round 6
// speedup vs baseline: 1.1544x; 1.1544x over previous
#include <cuda_runtime.h>
#include <cuda_fp16.h>
#include <cstdint>

#define NTOK 4096
#define HH   1024
#define VV   32000
#define VSP  250          // 250 * 128 = 32000 vocab splits
#define TTL  32           // 32 * 128 = 4096 token tiles
#define NKC  16           // 16 * 64 = 1024 k-chunks
#define ROWB 128          // 64 fp16 per row, XOR-swizzled (no pad)
#define TILEB (128*ROWB)  // 16384
#define STGB  (2*TILEB)   // A + B = 32768
#define NSTG  3
#define DSMEM (NSTG*STGB) // 98304

// ---------------- device scratch (no allocations allowed) -------------------
__device__ __align__(256) __half g_xb[(size_t)2*NTOK*HH];   // 16.8 MB
__device__ __align__(256) __half g_wb[(size_t)2*VV*HH];     // 131 MB
__device__ float g_pm[(size_t)2*NTOK*VSP];
__device__ float g_ps[(size_t)2*NTOK*VSP];
__device__ float g_sel[2*NTOK];
__device__ float g_bsum[32];
__device__ float g_bmsk[32];

__device__ __forceinline__ uint32_t smem_u32(const void* p){
    uint32_t a;
    asm("{ .reg .u64 t; cvta.to.shared.u64 t, %1; cvt.u32.u64 %0, t; }" : "=r"(a) : "l"(p));
    return a;
}

// ================= fp32 -> fp16 conversion (linear layout) ==================
__global__ void k_convert(const float* __restrict__ s0, const float* __restrict__ s1,
                          __half* __restrict__ dst, size_t per_model_vec4){
    size_t g = (size_t)blockIdx.x*blockDim.x + threadIdx.x;
    if (g >= 2*per_model_vec4) return;
    int m = (int)(g / per_model_vec4);
    size_t i = g - (size_t)m*per_model_vec4;
    const float* src = m ? s1 : s0;
    float4 v = reinterpret_cast<const float4*>(src)[i];
    __half2 lo = __floats2half2_rn(v.x, v.y);
    __half2 hi = __floats2half2_rn(v.z, v.w);
    uint2 o;
    o.x = *reinterpret_cast<uint32_t*>(&lo);
    o.y = *reinterpret_cast<uint32_t*>(&hi);
    reinterpret_cast<uint2*>(dst + (size_t)m*per_model_vec4*4)[i] = o;
}

// ================= main GEMM (mma.sync fp16) + fused online-LSE =============
// grid (VSP=250, TTL=32, 2), block 256, CTA tile 128x128, warp tile 64x32.
// 3-stage cp.async pipeline, XOR-swizzled smem rows, 1 sync per k-chunk.
__global__ void __launch_bounds__(256,2) k_gemm(){
    extern __shared__ __align__(16) unsigned char dsm[];
    const int tid = threadIdx.x, wid = tid>>5, lane = tid&31;
    const int vs = blockIdx.x, tt = blockIdx.y, model = blockIdx.z;
    const int wm = wid>>2, wn = wid&3;
    uint32_t sbase = smem_u32(dsm);
    const unsigned char* asrc = (const unsigned char*)(g_xb + ((size_t)model*NTOK + (size_t)tt*128)*HH);
    const unsigned char* bsrc = (const unsigned char*)(g_wb + ((size_t)model*VV   + (size_t)vs*128)*HH);

    float acc[4][4][4];
    #pragma unroll
    for (int a=0;a<4;a++)
        #pragma unroll
        for (int b=0;b<4;b++)
            #pragma unroll
            for (int c=0;c<4;c++) acc[a][b][c]=0.f;

    // loader: A 128 rows + B 128 rows, 128B each; 2048 x 16B; 256 thr x 8 it
    #define LOAD_CHUNK(kc) do{ \
        uint32_t _st = sbase + ((kc)%NSTG)*STGB; \
        _Pragma("unroll") \
        for (int it = 0; it < 8; it++){ \
            int idx = tid + it*256; \
            int row = (idx>>3)&127, grp = idx&7; \
            uint32_t d_ = _st + ((idx>>10)? TILEB:0) + row*ROWB + ((grp ^ (row&7))<<4); \
            const unsigned char* s_ = ((idx>>10)? bsrc:asrc) + (size_t)row*2048 + (size_t)(kc)*128 + (grp<<4); \
            asm volatile("cp.async.cg.shared.global [%0], [%1], 16;" :: "r"(d_), "l"(s_)); \
        } \
        asm volatile("cp.async.commit_group;"); \
    }while(0)

    LOAD_CHUNK(0);
    LOAD_CHUNK(1);
    #pragma unroll 1
    for (int kc = 0; kc < NKC; kc++){
        if (kc < NKC-2) asm volatile("cp.async.wait_group 1;");
        else            asm volatile("cp.async.wait_group 0;");
        __syncthreads();                          // compute(kc-1) done in all warps
        if (kc + 2 < NKC) LOAD_CHUNK(kc+2);       // overwrite stage (kc+2)%3
        uint32_t Ab = sbase + (kc%NSTG)*STGB, Bb = Ab + TILEB;
        #pragma unroll
        for (int ks = 0; ks < 4; ks++){
            uint32_t af[4][4], bf[2][4];
            #pragma unroll
            for (int mt = 0; mt < 4; mt++){
                int row = wm*64 + mt*16 + (lane&15);
                int bg  = ks*2 + (lane>>4);
                uint32_t a = Ab + row*ROWB + ((bg ^ (row&7))<<4);
                asm volatile("ldmatrix.sync.aligned.m8n8.x4.shared.b16 {%0,%1,%2,%3}, [%4];"
                    : "=r"(af[mt][0]),"=r"(af[mt][1]),"=r"(af[mt][2]),"=r"(af[mt][3]) : "r"(a));
            }
            #pragma unroll
            for (int p = 0; p < 2; p++){
                int row = wn*32 + p*16 + (lane&7) + ((lane>>4)<<3);
                int bg  = ks*2 + ((lane>>3)&1);
                uint32_t a = Bb + row*ROWB + ((bg ^ (row&7))<<4);
                asm volatile("ldmatrix.sync.aligned.m8n8.x4.shared.b16 {%0,%1,%2,%3}, [%4];"
                    : "=r"(bf[p][0]),"=r"(bf[p][1]),"=r"(bf[p][2]),"=r"(bf[p][3]) : "r"(a));
            }
            #pragma unroll
            for (int mt = 0; mt < 4; mt++)
                #pragma unroll
                for (int nt = 0; nt < 4; nt++){
                    uint32_t b0 = bf[nt>>1][(nt&1)*2], b1 = bf[nt>>1][(nt&1)*2+1];
                    asm volatile("mma.sync.aligned.m16n8k16.row.col.f32.f16.f16.f32 "
                        "{%0,%1,%2,%3}, {%4,%5,%6,%7}, {%8,%9}, {%0,%1,%2,%3};"
                        : "+f"(acc[mt][nt][0]),"+f"(acc[mt][nt][1]),"+f"(acc[mt][nt][2]),"+f"(acc[mt][nt][3])
                        : "r"(af[mt][0]),"r"(af[mt][1]),"r"(af[mt][2]),"r"(af[mt][3]),
                          "r"(b0),"r"(b1));
                }
        }
    }
    __syncthreads();

    // ---- fused epilogue: per-token-row (max, sumexp) over this 128-col slab -
    float* smM = (float*)dsm;           // [8][64]
    float* smS = smM + 8*64;
    int q = lane>>2;
    #pragma unroll
    for (int mt = 0; mt < 4; mt++){
        float m0=-3e38f, m1=-3e38f;
        #pragma unroll
        for (int nt = 0; nt < 4; nt++){
            m0 = fmaxf(m0, fmaxf(acc[mt][nt][0], acc[mt][nt][1]));
            m1 = fmaxf(m1, fmaxf(acc[mt][nt][2], acc[mt][nt][3]));
        }
        #pragma unroll
        for (int o = 1; o <= 2; o <<= 1){
            m0 = fmaxf(m0, __shfl_xor_sync(0xFFFFFFFFu, m0, o));
            m1 = fmaxf(m1, __shfl_xor_sync(0xFFFFFFFFu, m1, o));
        }
        float s0 = 0.f, s1 = 0.f;
        #pragma unroll
        for (int nt = 0; nt < 4; nt++){
            s0 += __expf(acc[mt][nt][0]-m0) + __expf(acc[mt][nt][1]-m0);
            s1 += __expf(acc[mt][nt][2]-m1) + __expf(acc[mt][nt][3]-m1);
        }
        #pragma unroll
        for (int o = 1; o <= 2; o <<= 1){
            s0 += __shfl_xor_sync(0xFFFFFFFFu, s0, o);
            s1 += __shfl_xor_sync(0xFFFFFFFFu, s1, o);
        }
        if ((lane&3) == 0){
            int r = mt*16 + q;
            smM[wid*64 + r]     = m0;  smS[wid*64 + r]     = s0;
            smM[wid*64 + r + 8] = m1;  smS[wid*64 + r + 8] = s1;
        }
    }
    __syncthreads();
    if (tid < 128){
        int wm2 = tid>>6, r = tid&63;
        float M = -3e38f;
        #pragma unroll
        for (int w = 0; w < 4; w++) M = fmaxf(M, smM[(wm2*4+w)*64 + r]);
        float S = 0.f;
        #pragma unroll
        for (int w = 0; w < 4; w++) S += smS[(wm2*4+w)*64 + r] * __expf(smM[(wm2*4+w)*64 + r] - M);
        int tok = tt*128 + tid;
        size_t o = ((size_t)(model*NTOK + tok))*VSP + vs;
        g_pm[o] = M; g_ps[o] = S;
    }
}

// ================= exact fp32 selected logits ================================
__global__ void k_sel(const float* __restrict__ x, const float* __restrict__ w,
                      const float* __restrict__ rx, const float* __restrict__ rw,
                      const int* __restrict__ ids){
    int gw = (int)((blockIdx.x*blockDim.x + threadIdx.x) >> 5);
    int lane = threadIdx.x & 31;
    if (gw >= 2*NTOK) return;
    int m = gw >> 12, t = gw & (NTOK-1);
    const float* X = m ? rx : x;
    const float* W = m ? rw : w;
    int id = ids[t];
    const float4* xa = (const float4*)(X + (size_t)t*HH);
    const float4* wa = (const float4*)(W + (size_t)id*HH);
    float acc = 0.f;
    #pragma unroll 8
    for (int i = lane; i < 256; i += 32){
        float4 a = xa[i], b = wa[i];
        acc += a.x*b.x + a.y*b.y + a.z*b.z + a.w*b.w;
    }
    #pragma unroll
    for (int o = 16; o; o >>= 1) acc += __shfl_xor_sync(0xFFFFFFFFu, acc, o);
    if (!lane) g_sel[gw] = acc;
}

// ================= per-token loss + deterministic block sums =================
__global__ void k_reduce(const float* __restrict__ adv, const int* __restrict__ mask){
    int t = blockIdx.x*128 + threadIdx.x;   // 32 x 128 = 4096
    float lse[2];
    #pragma unroll
    for (int m = 0; m < 2; m++){
        const float* pm = g_pm + ((size_t)(m*NTOK + t))*VSP;
        const float* ps = g_ps + ((size_t)(m*NTOK + t))*VSP;
        float mx = -3e38f;
        for (int v = 0; v < VSP; v++) mx = fmaxf(mx, pm[v]);
        float sv = 0.f;
        for (int v = 0; v < VSP; v++) sv += ps[v] * __expf(pm[v] - mx);
        lse[m] = mx + logf(sv);
    }
    float lp  = g_sel[t]        - lse[0];
    float rlp = g_sel[NTOK + t] - lse[1];
    float d = rlp - lp;
    float kl = expf(d) - d - 1.f;
    float mk = (float)mask[t];
    float pl = (-adv[t >> 10] + 0.1f*kl) * mk;

    __shared__ float sh[128], shm[128];
    sh[threadIdx.x] = pl; shm[threadIdx.x] = mk;
    __syncthreads();
    for (int o = 64; o; o >>= 1){
        if (threadIdx.x < o){ sh[threadIdx.x] += sh[threadIdx.x+o]; shm[threadIdx.x] += shm[threadIdx.x+o]; }
        __syncthreads();
    }
    if (!threadIdx.x){ g_bsum[blockIdx.x] = sh[0]; g_bmsk[blockIdx.x] = shm[0]; }
}

__global__ void k_final(float* out){
    float s = 0.f, m = 0.f;
    for (int i = 0; i < 32; i++){ s += g_bsum[i]; m += g_bmsk[i]; }
    out[0] = s / fmaxf(m, 1.f);
}

// ================= launch =====================================================
extern "C" void kernel_launch(void* const* d_in, const int* in_sizes, int n_in,
                              void* d_out, int out_size){
    const float* x   = (const float*)d_in[0];
    const float* w   = (const float*)d_in[1];
    const float* rx  = (const float*)d_in[2];
    const float* rw  = (const float*)d_in[3];
    const float* adv = (const float*)d_in[4];
    const int* ids   = (const int*)d_in[5];
    const int* mask  = (const int*)d_in[6];
    float* out = (float*)d_out;

    cudaFuncSetAttribute(k_gemm, cudaFuncAttributeMaxDynamicSharedMemorySize, DSMEM);

    {   size_t v4 = (size_t)NTOK*HH/4;   // hidden convert
        k_convert<<<(unsigned)((2*v4 + 255)/256), 256>>>(x, rx, g_xb, v4);
    }
    {   size_t v4 = (size_t)VV*HH/4;     // weight convert
        k_convert<<<(unsigned)((2*v4 + 255)/256), 256>>>(w, rw, g_wb, v4);
    }
    k_gemm<<<dim3(VSP, TTL, 2), 256, DSMEM>>>();
    k_sel<<<(2*NTOK*32 + 255)/256, 256>>>(x, w, rx, rw, ids);
    k_reduce<<<32, 128>>>(adv, mask);
    k_final<<<1, 1>>>(out);
}

// round 7
// speedup vs baseline: 1.2301x; 1.0655x over previous
#include <cuda_runtime.h>
#include <cuda_fp8.h>
#include <cstdint>

#define NTOK 4096
#define HH   1024
#define VV   32000
#define VSP  250          // 250 * 128 = 32000 vocab splits
#define TTL  32           // 32 * 128 = 4096 token tiles
#define NKC  8            // 8 * 128 = 1024 k-chunks (fp8: 128 elems = 128B)
#define ROWB 128          // 128 fp8 per row, XOR-swizzled
#define TILEB (128*ROWB)  // 16384
#define STGB  (2*TILEB)   // A + B = 32768
#define NSTG  3
#define DSMEM (NSTG*STGB) // 98304

// ---------------- device scratch (no allocations allowed) -------------------
__device__ __align__(256) unsigned char g_xb[(size_t)2*NTOK*HH];   // 8.4 MB
__device__ __align__(256) unsigned char g_wb[(size_t)2*VV*HH];     // 65.5 MB
__device__ float g_pm[(size_t)2*NTOK*VSP];
__device__ float g_ps[(size_t)2*NTOK*VSP];
__device__ float g_sel[2*NTOK];
__device__ float g_bsum[32];
__device__ float g_bmsk[32];

__device__ __forceinline__ uint32_t smem_u32(const void* p){
    uint32_t a;
    asm("{ .reg .u64 t; cvta.to.shared.u64 t, %1; cvt.u32.u64 %0, t; }" : "=r"(a) : "l"(p));
    return a;
}

// ================= fp32 -> e4m3 conversion (linear layout) ==================
__global__ void k_convert(const float* __restrict__ s0, const float* __restrict__ s1,
                          unsigned char* __restrict__ dst, size_t per_model_vec4){
    size_t g = (size_t)blockIdx.x*blockDim.x + threadIdx.x;
    if (g >= 2*per_model_vec4) return;
    int m = (int)(g / per_model_vec4);
    size_t i = g - (size_t)m*per_model_vec4;
    const float* src = m ? s1 : s0;
    float4 v = reinterpret_cast<const float4*>(src)[i];
    __nv_fp8x2_storage_t lo = __nv_cvt_float2_to_fp8x2(make_float2(v.x, v.y), __NV_SATFINITE, __NV_E4M3);
    __nv_fp8x2_storage_t hi = __nv_cvt_float2_to_fp8x2(make_float2(v.z, v.w), __NV_SATFINITE, __NV_E4M3);
    uint32_t o = (uint32_t)lo | ((uint32_t)hi << 16);
    reinterpret_cast<uint32_t*>(dst + (size_t)m*per_model_vec4*4)[i] = o;
}

// ================= main GEMM (mma.sync e4m3 k32) + fused online-LSE =========
// grid (VSP=250, TTL=32, 2), block 256, CTA tile 128x128, warp tile 64x32.
// 3-stage cp.async pipeline, XOR-swizzled 128B smem rows, 1 sync per k-chunk.
__global__ void __launch_bounds__(256,2) k_gemm(){
    extern __shared__ __align__(16) unsigned char dsm[];
    const int tid = threadIdx.x, wid = tid>>5, lane = tid&31;
    const int vs = blockIdx.x, tt = blockIdx.y, model = blockIdx.z;
    const int wm = wid>>2, wn = wid&3;
    uint32_t sbase = smem_u32(dsm);
    const unsigned char* asrc = g_xb + ((size_t)model*NTOK + (size_t)tt*128)*HH;
    const unsigned char* bsrc = g_wb + ((size_t)model*VV   + (size_t)vs*128)*HH;

    float acc[4][4][4];
    #pragma unroll
    for (int a=0;a<4;a++)
        #pragma unroll
        for (int b=0;b<4;b++)
            #pragma unroll
            for (int c=0;c<4;c++) acc[a][b][c]=0.f;

    // loader: A 128 rows + B 128 rows, 128B each; 2048 x 16B; 256 thr x 8 it
    #define LOAD_CHUNK(kc) do{ \
        uint32_t _st = sbase + ((kc)%NSTG)*STGB; \
        _Pragma("unroll") \
        for (int it = 0; it < 8; it++){ \
            int idx = tid + it*256; \
            int row = (idx>>3)&127, grp = idx&7; \
            uint32_t d_ = _st + ((idx>>10)? TILEB:0) + row*ROWB + ((grp ^ (row&7))<<4); \
            const unsigned char* s_ = ((idx>>10)? bsrc:asrc) + (size_t)row*HH + (size_t)(kc)*128 + (grp<<4); \
            asm volatile("cp.async.cg.shared.global [%0], [%1], 16;" :: "r"(d_), "l"(s_)); \
        } \
        asm volatile("cp.async.commit_group;"); \
    }while(0)

    LOAD_CHUNK(0);
    LOAD_CHUNK(1);
    #pragma unroll 1
    for (int kc = 0; kc < NKC; kc++){
        if (kc < NKC-2) asm volatile("cp.async.wait_group 1;");
        else            asm volatile("cp.async.wait_group 0;");
        __syncthreads();
        if (kc + 2 < NKC) LOAD_CHUNK(kc+2);
        uint32_t Ab = sbase + (kc%NSTG)*STGB, Bb = Ab + TILEB;
        #pragma unroll
        for (int ks = 0; ks < 4; ks++){   // each ks covers k=32 fp8
            uint32_t af[4][4], bf[2][4];
            #pragma unroll
            for (int mt = 0; mt < 4; mt++){
                int row = wm*64 + mt*16 + (lane&15);
                int bg  = ks*2 + (lane>>4);
                uint32_t a = Ab + row*ROWB + ((bg ^ (row&7))<<4);
                asm volatile("ldmatrix.sync.aligned.m8n8.x4.shared.b16 {%0,%1,%2,%3}, [%4];"
                    : "=r"(af[mt][0]),"=r"(af[mt][1]),"=r"(af[mt][2]),"=r"(af[mt][3]) : "r"(a));
            }
            #pragma unroll
            for (int p = 0; p < 2; p++){
                int row = wn*32 + p*16 + (lane&7) + ((lane>>4)<<3);
                int bg  = ks*2 + ((lane>>3)&1);
                uint32_t a = Bb + row*ROWB + ((bg ^ (row&7))<<4);
                asm volatile("ldmatrix.sync.aligned.m8n8.x4.shared.b16 {%0,%1,%2,%3}, [%4];"
                    : "=r"(bf[p][0]),"=r"(bf[p][1]),"=r"(bf[p][2]),"=r"(bf[p][3]) : "r"(a));
            }
            #pragma unroll
            for (int mt = 0; mt < 4; mt++)
                #pragma unroll
                for (int nt = 0; nt < 4; nt++){
                    uint32_t b0 = bf[nt>>1][(nt&1)*2], b1 = bf[nt>>1][(nt&1)*2+1];
                    asm volatile("mma.sync.aligned.m16n8k32.row.col.f32.e4m3.e4m3.f32 "
                        "{%0,%1,%2,%3}, {%4,%5,%6,%7}, {%8,%9}, {%0,%1,%2,%3};"
                        : "+f"(acc[mt][nt][0]),"+f"(acc[mt][nt][1]),"+f"(acc[mt][nt][2]),"+f"(acc[mt][nt][3])
                        : "r"(af[mt][0]),"r"(af[mt][1]),"r"(af[mt][2]),"r"(af[mt][3]),
                          "r"(b0),"r"(b1));
                }
        }
    }
    __syncthreads();

    // ---- fused epilogue: per-token-row (max, sumexp) over this 128-col slab -
    float* smM = (float*)dsm;           // [8][64]
    float* smS = smM + 8*64;
    int q = lane>>2;
    #pragma unroll
    for (int mt = 0; mt < 4; mt++){
        float m0=-3e38f, m1=-3e38f;
        #pragma unroll
        for (int nt = 0; nt < 4; nt++){
            m0 = fmaxf(m0, fmaxf(acc[mt][nt][0], acc[mt][nt][1]));
            m1 = fmaxf(m1, fmaxf(acc[mt][nt][2], acc[mt][nt][3]));
        }
        #pragma unroll
        for (int o = 1; o <= 2; o <<= 1){
            m0 = fmaxf(m0, __shfl_xor_sync(0xFFFFFFFFu, m0, o));
            m1 = fmaxf(m1, __shfl_xor_sync(0xFFFFFFFFu, m1, o));
        }
        float s0 = 0.f, s1 = 0.f;
        #pragma unroll
        for (int nt = 0; nt < 4; nt++){
            s0 += __expf(acc[mt][nt][0]-m0) + __expf(acc[mt][nt][1]-m0);
            s1 += __expf(acc[mt][nt][2]-m1) + __expf(acc[mt][nt][3]-m1);
        }
        #pragma unroll
        for (int o = 1; o <= 2; o <<= 1){
            s0 += __shfl_xor_sync(0xFFFFFFFFu, s0, o);
            s1 += __shfl_xor_sync(0xFFFFFFFFu, s1, o);
        }
        if ((lane&3) == 0){
            int r = mt*16 + q;
            smM[wid*64 + r]     = m0;  smS[wid*64 + r]     = s0;
            smM[wid*64 + r + 8] = m1;  smS[wid*64 + r + 8] = s1;
        }
    }
    __syncthreads();
    if (tid < 128){
        int wm2 = tid>>6, r = tid&63;
        float M = -3e38f;
        #pragma unroll
        for (int w = 0; w < 4; w++) M = fmaxf(M, smM[(wm2*4+w)*64 + r]);
        float S = 0.f;
        #pragma unroll
        for (int w = 0; w < 4; w++) S += smS[(wm2*4+w)*64 + r] * __expf(smM[(wm2*4+w)*64 + r] - M);
        int tok = tt*128 + tid;
        size_t o = ((size_t)(model*NTOK + tok))*VSP + vs;
        g_pm[o] = M; g_ps[o] = S;
    }
}

// ================= exact fp32 selected logits ================================
__global__ void k_sel(const float* __restrict__ x, const float* __restrict__ w,
                      const float* __restrict__ rx, const float* __restrict__ rw,
                      const int* __restrict__ ids){
    int gw = (int)((blockIdx.x*blockDim.x + threadIdx.x) >> 5);
    int lane = threadIdx.x & 31;
    if (gw >= 2*NTOK) return;
    int m = gw >> 12, t = gw & (NTOK-1);
    const float* X = m ? rx : x;
    const float* W = m ? rw : w;
    int id = ids[t];
    const float4* xa = (const float4*)(X + (size_t)t*HH);
    const float4* wa = (const float4*)(W + (size_t)id*HH);
    float acc = 0.f;
    #pragma unroll 8
    for (int i = lane; i < 256; i += 32){
        float4 a = xa[i], b = wa[i];
        acc += a.x*b.x + a.y*b.y + a.z*b.z + a.w*b.w;
    }
    #pragma unroll
    for (int o = 16; o; o >>= 1) acc += __shfl_xor_sync(0xFFFFFFFFu, acc, o);
    if (!lane) g_sel[gw] = acc;
}

// ================= per-token loss + deterministic block sums =================
__global__ void k_reduce(const float* __restrict__ adv, const int* __restrict__ mask){
    int t = blockIdx.x*128 + threadIdx.x;   // 32 x 128 = 4096
    float lse[2];
    #pragma unroll
    for (int m = 0; m < 2; m++){
        const float* pm = g_pm + ((size_t)(m*NTOK + t))*VSP;
        const float* ps = g_ps + ((size_t)(m*NTOK + t))*VSP;
        float mx = -3e38f;
        for (int v = 0; v < VSP; v++) mx = fmaxf(mx, pm[v]);
        float sv = 0.f;
        for (int v = 0; v < VSP; v++) sv += ps[v] * __expf(pm[v] - mx);
        lse[m] = mx + logf(sv);
    }
    float lp  = g_sel[t]        - lse[0];
    float rlp = g_sel[NTOK + t] - lse[1];
    float d = rlp - lp;
    float kl = expf(d) - d - 1.f;
    float mk = (float)mask[t];
    float pl = (-adv[t >> 10] + 0.1f*kl) * mk;

    __shared__ float sh[128], shm[128];
    sh[threadIdx.x] = pl; shm[threadIdx.x] = mk;
    __syncthreads();
    for (int o = 64; o; o >>= 1){
        if (threadIdx.x < o){ sh[threadIdx.x] += sh[threadIdx.x+o]; shm[threadIdx.x] += shm[threadIdx.x+o]; }
        __syncthreads();
    }
    if (!threadIdx.x){ g_bsum[blockIdx.x] = sh[0]; g_bmsk[blockIdx.x] = shm[0]; }
}

__global__ void k_final(float* out){
    float s = 0.f, m = 0.f;
    for (int i = 0; i < 32; i++){ s += g_bsum[i]; m += g_bmsk[i]; }
    out[0] = s / fmaxf(m, 1.f);
}

// ================= launch =====================================================
// NOTE: k_sel launched BEFORE k_gemm (no dependency) so ncu's skip window
// lands on k_gemm next round.
extern "C" void kernel_launch(void* const* d_in, const int* in_sizes, int n_in,
                              void* d_out, int out_size){
    const float* x   = (const float*)d_in[0];
    const float* w   = (const float*)d_in[1];
    const float* rx  = (const float*)d_in[2];
    const float* rw  = (const float*)d_in[3];
    const float* adv = (const float*)d_in[4];
    const int* ids   = (const int*)d_in[5];
    const int* mask  = (const int*)d_in[6];
    float* out = (float*)d_out;

    cudaFuncSetAttribute(k_gemm, cudaFuncAttributeMaxDynamicSharedMemorySize, DSMEM);

    {   size_t v4 = (size_t)NTOK*HH/4;   // hidden convert
        k_convert<<<(unsigned)((2*v4 + 255)/256), 256>>>(x, rx, g_xb, v4);
    }
    {   size_t v4 = (size_t)VV*HH/4;     // weight convert
        k_convert<<<(unsigned)((2*v4 + 255)/256), 256>>>(w, rw, g_wb, v4);
    }
    k_sel<<<(2*NTOK*32 + 255)/256, 256>>>(x, w, rx, rw, ids);
    k_gemm<<<dim3(VSP, TTL, 2), 256, DSMEM>>>();
    k_reduce<<<32, 128>>>(adv, mask);
    k_final<<<1, 1>>>(out);
}